// round 3
// baseline (speedup 1.0000x reference)
#include <cuda_runtime.h>
#include <math.h>

// PDELayer: 8192 x (48x48) grids, 100 explicit diffusion steps.
// One CTA per grid. 16x16 threads, each owns a 3x3 register tile.
// Double-buffered shared memory (50x52 padded), 1 barrier per step.
// Reflect halo is constant over time (reference pads once, updates interior only).

#define NG     48      // grid size
#define PR     50      // padded rows
#define SS     52      // padded row stride (floats)
#define NSTEPS 100

__device__ __forceinline__ void step_tile(
    const float* __restrict__ cur, float* __restrict__ nxt,
    float u[3][3], const float A[3], const float Bc[3], const float cc[3][3],
    int r0, int c0)
{
    float top[3], bot[3], lef[3], rig[3];
#pragma unroll
    for (int k = 0; k < 3; k++) {
        top[k] = cur[(r0 - 1) * SS + c0 + k];
        bot[k] = cur[(r0 + 3) * SS + c0 + k];
        lef[k] = cur[(r0 + k) * SS + c0 - 1];
        rig[k] = cur[(r0 + k) * SS + c0 + 3];
    }
    float nv[3][3];
#pragma unroll
    for (int r = 0; r < 3; r++) {
#pragma unroll
        for (int c = 0; c < 3; c++) {
            float up = (r == 0) ? top[c] : u[r - 1][c];
            float dn = (r == 2) ? bot[c] : u[r + 1][c];
            float lf = (c == 0) ? lef[r] : u[r][c - 1];
            float rt = (c == 2) ? rig[r] : u[r][c + 1];
            float v = cc[r][c] * u[r][c];
            v = fmaf(A[r],  up + dn, v);
            v = fmaf(Bc[c], lf + rt, v);
            nv[r][c] = v;
        }
    }
#pragma unroll
    for (int r = 0; r < 3; r++)
#pragma unroll
        for (int c = 0; c < 3; c++) {
            nxt[(r0 + r) * SS + c0 + c] = nv[r][c];
            u[r][c] = nv[r][c];
        }
    __syncthreads();
}

__global__ __launch_bounds__(256, 4)
void pde_stencil_kernel(const float* __restrict__ u0,
                        const float* __restrict__ a1p, const float* __restrict__ a2p,
                        const float* __restrict__ a3p, const float* __restrict__ b1p,
                        const float* __restrict__ b2p, const float* __restrict__ b3p,
                        float* __restrict__ out)
{
    __shared__ float buf0[PR * SS];
    __shared__ float buf1[PR * SS];

    const int b   = blockIdx.x;
    const int tid = threadIdx.x;
    const int tx  = tid & 15;
    const int ty  = tid >> 4;

    const float* gin  = u0  + (size_t)b * (NG * NG);
    float*       gout = out + (size_t)b * (NG * NG);

    // ---- load interior into buf0 (coalesced) ----
#pragma unroll
    for (int k = 0; k < 9; k++) {
        int c = tid + k * 256;              // 0 .. 2303
        int i = c / NG, j = c % NG;
        buf0[(i + 1) * SS + (j + 1)] = gin[c];
    }
    __syncthreads();

    // ---- reflect halo (time-invariant) into BOTH buffers ----
    // padded idx p maps to source interior padded idx: 0->2, 49->47, else p
    if (tid < 196) {
        int ii, jj;
        if      (tid < 50)  { ii = 0;          jj = tid;       }
        else if (tid < 100) { ii = 49;         jj = tid - 50;  }
        else if (tid < 148) { ii = tid - 99;   jj = 0;         }  // ii in 1..48
        else                { ii = tid - 147;  jj = 49;        }  // ii in 1..48
        int si = (ii == 0) ? 2 : (ii == 49) ? 47 : ii;
        int sj = (jj == 0) ? 2 : (jj == 49) ? 47 : jj;
        float v = buf0[si * SS + sj];
        buf0[ii * SS + jj] = v;
        buf1[ii * SS + jj] = v;
    }

    // ---- per-thread coefficients (alpha by row, beta by col) ----
    const float aw1 = fabsf(*a1p), aw2 = fabsf(*a2p), aw3 = fabsf(*a3p);
    const float bw1 = fabsf(*b1p), bw2 = fabsf(*b2p), bw3 = fabsf(*b3p);
    const float CA = 0.1152f;   // 0.5 * DT / DX^2 = 0.5 * 1e-4 * 48^2
    const float CB = 0.2304f;   // DT / DY^2
    const float TP = 6.283185307179586f;
    const float INV47 = 1.0f / 47.0f;

    const int r0 = 1 + 3 * ty;   // padded row base of this thread's tile
    const int c0 = 1 + 3 * tx;   // padded col base

    float A[3], Bc[3], cc[3][3];
#pragma unroll
    for (int r = 0; r < 3; r++) {
        float t = (float)(3 * ty + r) * INV47;
        A[r] = CA * (aw1 + aw2 * sinf(TP * t) + aw3 * cosf(TP * t));
    }
#pragma unroll
    for (int c = 0; c < 3; c++) {
        float t = (float)(3 * tx + c) * INV47;
        Bc[c] = CB * (bw1 + bw2 * cosf(TP * t) + bw3 * sinf(TP * t));
    }
#pragma unroll
    for (int r = 0; r < 3; r++)
#pragma unroll
        for (int c = 0; c < 3; c++)
            cc[r][c] = 1.0f - 2.0f * (A[r] + Bc[c]);

    __syncthreads();   // halo visible; interior of buf0 valid

    // ---- own 3x3 tile into registers ----
    float u[3][3];
#pragma unroll
    for (int r = 0; r < 3; r++)
#pragma unroll
        for (int c = 0; c < 3; c++)
            u[r][c] = buf0[(r0 + r) * SS + c0 + c];

    // ---- time loop: 100 steps, ping-pong buffers, 1 barrier/step ----
    for (int s = 0; s < NSTEPS; s += 2) {
        step_tile(buf0, buf1, u, A, Bc, cc, r0, c0);
        step_tile(buf1, buf0, u, A, Bc, cc, r0, c0);
    }
    // final state (after step 99) is in buf0; last __syncthreads done in step_tile

    // ---- coalesced writeback ----
#pragma unroll
    for (int k = 0; k < 9; k++) {
        int c = tid + k * 256;
        int i = c / NG, j = c % NG;
        gout[c] = buf0[(i + 1) * SS + (j + 1)];
    }
}

extern "C" void kernel_launch(void* const* d_in, const int* in_sizes, int n_in,
                              void* d_out, int out_size)
{
    const float* u0 = (const float*)d_in[0];
    const float* a1 = (const float*)d_in[1];
    const float* a2 = (const float*)d_in[2];
    const float* a3 = (const float*)d_in[3];
    const float* b1 = (const float*)d_in[4];
    const float* b2 = (const float*)d_in[5];
    const float* b3 = (const float*)d_in[6];
    float* out = (float*)d_out;

    int nb = in_sizes[0] / (NG * NG);   // 8192
    pde_stencil_kernel<<<nb, 256>>>(u0, a1, a2, a3, b1, b2, b3, out);
}

// round 6
// speedup vs baseline: 1.8372x; 1.8372x over previous
#include <cuda_runtime.h>
#include <math.h>

// PDELayer: 8192 x (48x48) grids, 100 explicit diffusion steps.
// One CTA per grid. 64 threads (16x4), each owns a 3-wide x 12-tall register tile.
// Double-buffered shared memory; only tile PERIMETER cells are exchanged via SMEM.
// Bank-conflict-free: with SS=52, TH=12 -> 12*SS = 16 (mod 32), and 3*tx is a
// bijection mod 16, so every row/col LDS/STS wavefront hits 32 distinct banks.
// Reflect halo is time-invariant (reference pads once, updates interior only).

#define NG     48
#define PR     50      // padded rows
#define SS     52      // padded row stride (floats)
#define NSTEPS 100
#define TW     3       // tile width  (cols per thread)
#define TH     12      // tile height (rows per thread)

__device__ __forceinline__ void step_tile(
    const float* __restrict__ cur, float* __restrict__ nxt,
    float u[TH][TW], const float A[TH], const float B0, const float B1, const float B2,
    int R0, int C0)
{
    // time-constant-halo-backed neighbor rows
    float top0 = cur[(R0 - 1) * SS + C0 + 0];
    float top1 = cur[(R0 - 1) * SS + C0 + 1];
    float top2 = cur[(R0 - 1) * SS + C0 + 2];
    float bot0 = cur[(R0 + TH) * SS + C0 + 0];
    float bot1 = cur[(R0 + TH) * SS + C0 + 1];
    float bot2 = cur[(R0 + TH) * SS + C0 + 2];

    float pv0 = 0.f, pv1 = 0.f, pv2 = 0.f;   // old u[r-1]
#pragma unroll
    for (int r = 0; r < TH; r++) {
        float lf = cur[(R0 + r) * SS + C0 - 1];
        float rt = cur[(R0 + r) * SS + C0 + TW];

        float c0 = u[r][0], c1 = u[r][1], c2 = u[r][2];

        float up0 = (r == 0) ? top0 : pv0;
        float up1 = (r == 0) ? top1 : pv1;
        float up2 = (r == 0) ? top2 : pv2;
        float dn0 = (r == TH - 1) ? bot0 : u[r + 1][0];
        float dn1 = (r == TH - 1) ? bot1 : u[r + 1][1];
        float dn2 = (r == TH - 1) ? bot2 : u[r + 1][2];

        // v = u + A[r]*(up+dn-2u) + B[c]*(lf+rt-2u)   (6 fma-pipe ops/cell)
        float sx0 = fmaf(-2.0f, c0, up0 + dn0);
        float sy0 = fmaf(-2.0f, c0, lf + c1);
        float n0  = fmaf(B0, sy0, fmaf(A[r], sx0, c0));

        float sx1 = fmaf(-2.0f, c1, up1 + dn1);
        float sy1 = fmaf(-2.0f, c1, c0 + c2);
        float n1  = fmaf(B1, sy1, fmaf(A[r], sx1, c1));

        float sx2 = fmaf(-2.0f, c2, up2 + dn2);
        float sy2 = fmaf(-2.0f, c2, c1 + rt);
        float n2  = fmaf(B2, sy2, fmaf(A[r], sx2, c2));

        // store only perimeter cells (others are never read from SMEM)
        float* nrow = &nxt[(R0 + r) * SS + C0];
        if (r == 0 || r == TH - 1) {
            nrow[0] = n0; nrow[1] = n1; nrow[2] = n2;
        } else {
            nrow[0] = n0; nrow[2] = n2;
        }

        pv0 = c0; pv1 = c1; pv2 = c2;
        u[r][0] = n0; u[r][1] = n1; u[r][2] = n2;
    }
    __syncthreads();
}

__global__ __launch_bounds__(64)
void pde_stencil_kernel(const float* __restrict__ u0,
                        const float* __restrict__ a1p, const float* __restrict__ a2p,
                        const float* __restrict__ a3p, const float* __restrict__ b1p,
                        const float* __restrict__ b2p, const float* __restrict__ b3p,
                        float* __restrict__ out)
{
    __shared__ float buf0[PR * SS];
    __shared__ float buf1[PR * SS];

    const int b   = blockIdx.x;
    const int tid = threadIdx.x;
    const int tx  = tid & 15;     // tile col 0..15
    const int ty  = tid >> 4;     // tile row 0..3

    const float* gin  = u0  + (size_t)b * (NG * NG);
    float*       gout = out + (size_t)b * (NG * NG);

    // ---- coalesced load of interior into buf0 ----
#pragma unroll
    for (int k = 0; k < 36; k++) {
        int c = tid + 64 * k;               // 0..2303
        int i = c / NG, j = c % NG;
        buf0[(i + 1) * SS + (j + 1)] = gin[c];
    }
    __syncthreads();

    // ---- reflect halo (time-invariant) into BOTH buffers ----
    for (int h = tid; h < 196; h += 64) {
        int ii, jj;
        if      (h < 50)  { ii = 0;         jj = h;        }
        else if (h < 100) { ii = 49;        jj = h - 50;   }
        else if (h < 148) { ii = h - 99;    jj = 0;        }   // 1..48
        else              { ii = h - 147;   jj = 49;       }   // 1..48
        int si = (ii == 0) ? 2 : (ii == 49) ? 47 : ii;
        int sj = (jj == 0) ? 2 : (jj == 49) ? 47 : jj;
        float v = buf0[si * SS + sj];
        buf0[ii * SS + jj] = v;
        buf1[ii * SS + jj] = v;
    }

    // ---- per-thread coefficients ----
    const float aw1 = fabsf(*a1p), aw2 = fabsf(*a2p), aw3 = fabsf(*a3p);
    const float bw1 = fabsf(*b1p), bw2 = fabsf(*b2p), bw3 = fabsf(*b3p);
    const float CA = 0.1152f;                 // 0.5*DT/DX^2
    const float CB = 0.2304f;                 // DT/DY^2
    const float TP = 6.283185307179586f;
    const float INV47 = 1.0f / 47.0f;

    const int R0 = 1 + TH * ty;   // padded base row
    const int C0 = 1 + TW * tx;   // padded base col

    float A[TH];
#pragma unroll
    for (int r = 0; r < TH; r++) {
        float t = (float)(TH * ty + r) * INV47;
        A[r] = CA * (aw1 + aw2 * sinf(TP * t) + aw3 * cosf(TP * t));
    }
    float Bv[TW];
#pragma unroll
    for (int c = 0; c < TW; c++) {
        float t = (float)(TW * tx + c) * INV47;
        Bv[c] = CB * (bw1 + bw2 * cosf(TP * t) + bw3 * sinf(TP * t));
    }
    const float B0 = Bv[0], B1 = Bv[1], B2 = Bv[2];

    __syncthreads();   // halo + interior visible

    // ---- own tile into registers ----
    float u[TH][TW];
#pragma unroll
    for (int r = 0; r < TH; r++)
#pragma unroll
        for (int c = 0; c < TW; c++)
            u[r][c] = buf0[(R0 + r) * SS + C0 + c];

    // ---- 100 steps, ping-pong perimeter buffers, 1 barrier/step ----
    for (int s = 0; s < NSTEPS; s += 2) {
        step_tile(buf0, buf1, u, A, B0, B1, B2, R0, C0);
        step_tile(buf1, buf0, u, A, B0, B1, B2, R0, C0);
    }

    // ---- writeback straight from registers ----
#pragma unroll
    for (int r = 0; r < TH; r++)
#pragma unroll
        for (int c = 0; c < TW; c++)
            gout[(TH * ty + r) * NG + (TW * tx + c)] = u[r][c];
}

extern "C" void kernel_launch(void* const* d_in, const int* in_sizes, int n_in,
                              void* d_out, int out_size)
{
    const float* u0 = (const float*)d_in[0];
    const float* a1 = (const float*)d_in[1];
    const float* a2 = (const float*)d_in[2];
    const float* a3 = (const float*)d_in[3];
    const float* b1 = (const float*)d_in[4];
    const float* b2 = (const float*)d_in[5];
    const float* b3 = (const float*)d_in[6];
    float* out = (float*)d_out;

    int nb = in_sizes[0] / (NG * NG);   // 8192
    pde_stencil_kernel<<<nb, 64>>>(u0, a1, a2, a3, b1, b2, b3, out);
}